// round 1
// baseline (speedup 1.0000x reference)
#include <cuda_runtime.h>
#include <math.h>

// ---------------- problem constants ----------------
#define BATCH 2
#define TT    2048
#define TOK   4096          // BATCH*TT
#define DD    1024
#define DI    2048
#define XZN   4096          // 2*DI
#define NSTATE 16
#define DTR   64
#define PROJN 96            // DTR + 2*NSTATE
#define DFF   2048
#define NE    8
#define CAP   4096          // max tokens per expert

// ---------------- scratch (static device memory; no allocs) ----------------
__device__ float g_hnorm[TOK * DD];          // 16 MB
__device__ float g_xz[TOK * XZN];            // 64 MB
__device__ float g_xc[TOK * DI];             // 32 MB
__device__ float g_proj[TOK * PROJN];        // 1.5 MB
__device__ float g_dt[TOK * DI];             // 32 MB
__device__ float g_y[TOK * DI];              // 32 MB
__device__ float g_hmoein[TOK * DD];         // 16 MB
__device__ float g_h1[NE * CAP * DFF];       // 256 MB
__device__ float g_ye[NE * CAP * DD];        // 128 MB
__device__ int   g_cnt[NE];
__device__ int   g_list[NE * CAP];
__device__ int   g_slot[TOK * 2];
__device__ float g_wgt[TOK * 2];

// ---------------- LayerNorm ----------------
__global__ __launch_bounds__(256) void ln_kernel(
    const float* __restrict__ x, float* __restrict__ out,
    const float* __restrict__ g, const float* __restrict__ b)
{
    int tok = blockIdx.x;
    int i = threadIdx.x << 2;
    const float* xr = x + (size_t)tok * DD;
    float4 v = *(const float4*)&xr[i];
    float s  = v.x + v.y + v.z + v.w;
    float s2 = v.x*v.x + v.y*v.y + v.z*v.z + v.w*v.w;
    #pragma unroll
    for (int o = 16; o > 0; o >>= 1) {
        s  += __shfl_xor_sync(0xffffffffu, s,  o);
        s2 += __shfl_xor_sync(0xffffffffu, s2, o);
    }
    __shared__ float sh[16];
    int w = threadIdx.x >> 5;
    if ((threadIdx.x & 31) == 0) { sh[w] = s; sh[8 + w] = s2; }
    __syncthreads();
    s = 0.f; s2 = 0.f;
    #pragma unroll
    for (int k = 0; k < 8; k++) { s += sh[k]; s2 += sh[8 + k]; }
    float mu  = s * (1.0f / DD);
    float var = s2 * (1.0f / DD) - mu * mu;
    float r = rsqrtf(var + 1e-5f);
    float4 gv = *(const float4*)&g[i];
    float4 bv = *(const float4*)&b[i];
    float4 o4;
    o4.x = (v.x - mu) * r * gv.x + bv.x;
    o4.y = (v.y - mu) * r * gv.y + bv.y;
    o4.z = (v.z - mu) * r * gv.z + bv.z;
    o4.w = (v.w - mu) * r * gv.w + bv.w;
    *(float4*)&out[(size_t)tok * DD + i] = o4;
}

// ---------------- generic NT GEMM: C[M,N] = A[M,K] * B[N,K]^T (+bias,+resid,act) --------
// act: 0 none, 1 silu, 2 softplus
__global__ __launch_bounds__(256) void gemm_nt(
    const float* __restrict__ A, int lda,
    const float* __restrict__ B, int ldb,
    float* __restrict__ C, int ldc,
    int M, int N, int K,
    const float* __restrict__ bias,
    const float* __restrict__ resid,
    int act)
{
    __shared__ float As[16][68];
    __shared__ float Bs[16][68];
    int tid = threadIdx.x;
    int m0 = blockIdx.y * 64, n0 = blockIdx.x * 64;
    int lr = tid >> 2;
    int lk = (tid & 3) << 2;
    int tx = tid & 15, ty = tid >> 4;
    float acc[4][4] = {};
    const float* Arow = A + (size_t)(m0 + lr) * lda + lk;
    const float* Brow = B + (size_t)(n0 + lr) * ldb + lk;
    bool am = (m0 + lr) < M;
    bool bn = (n0 + lr) < N;
    for (int k0 = 0; k0 < K; k0 += 16) {
        float4 av = make_float4(0.f,0.f,0.f,0.f), bv = make_float4(0.f,0.f,0.f,0.f);
        if (am) av = *(const float4*)(Arow + k0);
        if (bn) bv = *(const float4*)(Brow + k0);
        __syncthreads();
        As[lk+0][lr]=av.x; As[lk+1][lr]=av.y; As[lk+2][lr]=av.z; As[lk+3][lr]=av.w;
        Bs[lk+0][lr]=bv.x; Bs[lk+1][lr]=bv.y; Bs[lk+2][lr]=bv.z; Bs[lk+3][lr]=bv.w;
        __syncthreads();
        #pragma unroll
        for (int k = 0; k < 16; k++) {
            float4 a = *(const float4*)&As[k][ty << 2];
            float4 b = *(const float4*)&Bs[k][tx << 2];
            acc[0][0]+=a.x*b.x; acc[0][1]+=a.x*b.y; acc[0][2]+=a.x*b.z; acc[0][3]+=a.x*b.w;
            acc[1][0]+=a.y*b.x; acc[1][1]+=a.y*b.y; acc[1][2]+=a.y*b.z; acc[1][3]+=a.y*b.w;
            acc[2][0]+=a.z*b.x; acc[2][1]+=a.z*b.y; acc[2][2]+=a.z*b.z; acc[2][3]+=a.z*b.w;
            acc[3][0]+=a.w*b.x; acc[3][1]+=a.w*b.y; acc[3][2]+=a.w*b.z; acc[3][3]+=a.w*b.w;
        }
    }
    #pragma unroll
    for (int i = 0; i < 4; i++) {
        int m = m0 + (ty << 2) + i;
        if (m >= M) continue;
        #pragma unroll
        for (int j = 0; j < 4; j++) {
            int n = n0 + (tx << 2) + j;
            if (n >= N) continue;
            float c = acc[i][j];
            if (bias) c += bias[n];
            if (resid) c += resid[(size_t)m * ldc + n];
            if (act == 1) c = c / (1.f + __expf(-c));
            else if (act == 2) c = (c > 20.f) ? c : log1pf(__expf(c));
            C[(size_t)m * ldc + n] = c;
        }
    }
}

// ---------------- causal depthwise conv (KC=4) + SiLU ----------------
__global__ __launch_bounds__(256) void conv_silu_kernel(
    const float* __restrict__ xz,
    const float* __restrict__ cw,
    const float* __restrict__ cb,
    float* __restrict__ xc)
{
    int idx = blockIdx.x * 256 + threadIdx.x;   // over TOK*DI
    int d = idx & (DI - 1);
    int m = idx >> 11;      // token
    int t = m & (TT - 1);
    float acc = cb[d];
    float4 w = *(const float4*)&cw[d * 4];
    const float* base = xz + (size_t)m * XZN + d;
    if (t >= 3) acc += w.x * base[-3 * XZN];
    if (t >= 2) acc += w.y * base[-2 * XZN];
    if (t >= 1) acc += w.z * base[-XZN];
    acc += w.w * base[0];
    xc[idx] = acc / (1.f + __expf(-acc));
}

// ---------------- selective scan ----------------
// warp = 8 channels x (4 lanes x 4 states). no __syncthreads in loop.
__global__ __launch_bounds__(256) void scan_kernel(
    const float* __restrict__ proj,
    const float* __restrict__ xc,
    const float* __restrict__ dt,
    const float* __restrict__ xz,
    const float* __restrict__ A_log,
    const float* __restrict__ D_skip,
    float* __restrict__ ybuf)
{
    int b = blockIdx.y;
    int lane = threadIdx.x & 31;
    int ch = lane >> 2, ng = lane & 3;
    int d = (blockIdx.x * 8 + (threadIdx.x >> 5)) * 8 + ch;

    float4 Al = *(const float4*)&A_log[(size_t)d * NSTATE + ng * 4];
    float a0 = -__expf(Al.x), a1 = -__expf(Al.y), a2 = -__expf(Al.z), a3 = -__expf(Al.w);
    float h0 = 0.f, h1 = 0.f, h2 = 0.f, h3 = 0.f;
    float dsk = D_skip[d];
    size_t tokbase = (size_t)b * TT;

    for (int t = 0; t < TT; t++) {
        size_t tok = tokbase + t;
        float4 Bv = *(const float4*)&proj[tok * PROJN + DTR + ng * 4];
        float4 Cv = *(const float4*)&proj[tok * PROJN + DTR + NSTATE + ng * 4];
        float xt  = xc[tok * DI + d];
        float dtt = dt[tok * DI + d];
        float dx  = dtt * xt;
        h0 = __expf(dtt * a0) * h0 + dx * Bv.x;
        h1 = __expf(dtt * a1) * h1 + dx * Bv.y;
        h2 = __expf(dtt * a2) * h2 + dx * Bv.z;
        h3 = __expf(dtt * a3) * h3 + dx * Bv.w;
        float y = h0 * Cv.x + h1 * Cv.y + h2 * Cv.z + h3 * Cv.w;
        y += __shfl_xor_sync(0xffffffffu, y, 1);
        y += __shfl_xor_sync(0xffffffffu, y, 2);
        if (ng == 0) {
            float z = xz[tok * XZN + DI + d];
            float sil = z / (1.f + __expf(-z));
            ybuf[tok * DI + d] = (y + xt * dsk) * sil;
        }
    }
}

// ---------------- router: softmax + top2 + expert list build ----------------
__global__ __launch_bounds__(256) void router_kernel(
    const float* __restrict__ xin,
    const float* __restrict__ rw,
    float* __restrict__ probs_out)
{
    int warp = threadIdx.x >> 5, lane = threadIdx.x & 31;
    int tok = blockIdx.x * 8 + warp;
    const float* xr = xin + (size_t)tok * DD;
    float acc[8] = {};
    for (int c = lane; c < DD; c += 32) {
        float xv = xr[c];
        #pragma unroll
        for (int e = 0; e < 8; e++) acc[e] += xv * rw[e * DD + c];
    }
    #pragma unroll
    for (int e = 0; e < 8; e++)
        #pragma unroll
        for (int o = 16; o > 0; o >>= 1) acc[e] += __shfl_xor_sync(0xffffffffu, acc[e], o);
    if (lane == 0) {
        float mx = acc[0];
        #pragma unroll
        for (int e = 1; e < 8; e++) mx = fmaxf(mx, acc[e]);
        float p[8], s = 0.f;
        #pragma unroll
        for (int e = 0; e < 8; e++) { p[e] = __expf(acc[e] - mx); s += p[e]; }
        float inv = 1.f / s;
        #pragma unroll
        for (int e = 0; e < 8; e++) { p[e] *= inv; probs_out[(size_t)tok * 8 + e] = p[e]; }
        int i0 = 0; float v0 = p[0];
        #pragma unroll
        for (int e = 1; e < 8; e++) if (p[e] > v0) { v0 = p[e]; i0 = e; }
        int i1 = -1; float v1 = -1.f;
        #pragma unroll
        for (int e = 0; e < 8; e++) if (e != i0 && p[e] > v1) { v1 = p[e]; i1 = e; }
        float wn = 1.f / (v0 + v1);
        int p0 = atomicAdd(&g_cnt[i0], 1);
        int p1 = atomicAdd(&g_cnt[i1], 1);
        g_list[i0 * CAP + p0] = tok;
        g_list[i1 * CAP + p1] = tok;
        g_slot[tok * 2 + 0] = i0 * CAP + p0;
        g_slot[tok * 2 + 1] = i1 * CAP + p1;
        g_wgt[tok * 2 + 0] = v0 * wn;
        g_wgt[tok * 2 + 1] = v1 * wn;
    }
}

__global__ void zero_cnt_kernel() { if (threadIdx.x < NE) g_cnt[threadIdx.x] = 0; }

// ---------------- grouped MoE GEMM (per-expert, dynamic M, optional row-gather) --------
__global__ __launch_bounds__(256) void moe_gemm(
    const float* __restrict__ A, int lda, size_t strideA,
    const float* __restrict__ B, int ldb, size_t strideB,
    float* __restrict__ C, int ldc, size_t strideC,
    int N, int K,
    const float* __restrict__ bias, int strideBias,
    int act, int gather)
{
    int e = blockIdx.z;
    int M = g_cnt[e];
    int m0 = blockIdx.y * 64;
    if (m0 >= M) return;
    int n0 = blockIdx.x * 64;

    __shared__ float As[16][68];
    __shared__ float Bs[16][68];
    int tid = threadIdx.x;
    int lr = tid >> 2;
    int lk = (tid & 3) << 2;
    int tx = tid & 15, ty = tid >> 4;
    float acc[4][4] = {};

    int mrow = m0 + lr;
    bool am = mrow < M;
    size_t arow = 0;
    if (gather) { if (am) arow = (size_t)g_list[e * CAP + mrow]; }
    else arow = (size_t)mrow;
    const float* Ap = A + strideA * e + arow * lda + lk;
    const float* Bp = B + strideB * e + (size_t)(n0 + lr) * ldb + lk;
    bool bn = (n0 + lr) < N;

    for (int k0 = 0; k0 < K; k0 += 16) {
        float4 av = make_float4(0.f,0.f,0.f,0.f), bv = make_float4(0.f,0.f,0.f,0.f);
        if (am) av = *(const float4*)(Ap + k0);
        if (bn) bv = *(const float4*)(Bp + k0);
        __syncthreads();
        As[lk+0][lr]=av.x; As[lk+1][lr]=av.y; As[lk+2][lr]=av.z; As[lk+3][lr]=av.w;
        Bs[lk+0][lr]=bv.x; Bs[lk+1][lr]=bv.y; Bs[lk+2][lr]=bv.z; Bs[lk+3][lr]=bv.w;
        __syncthreads();
        #pragma unroll
        for (int k = 0; k < 16; k++) {
            float4 a = *(const float4*)&As[k][ty << 2];
            float4 b = *(const float4*)&Bs[k][tx << 2];
            acc[0][0]+=a.x*b.x; acc[0][1]+=a.x*b.y; acc[0][2]+=a.x*b.z; acc[0][3]+=a.x*b.w;
            acc[1][0]+=a.y*b.x; acc[1][1]+=a.y*b.y; acc[1][2]+=a.y*b.z; acc[1][3]+=a.y*b.w;
            acc[2][0]+=a.z*b.x; acc[2][1]+=a.z*b.y; acc[2][2]+=a.z*b.z; acc[2][3]+=a.z*b.w;
            acc[3][0]+=a.w*b.x; acc[3][1]+=a.w*b.y; acc[3][2]+=a.w*b.z; acc[3][3]+=a.w*b.w;
        }
    }
    float* Cp = C + strideC * e;
    const float* bp = bias + (size_t)strideBias * e;
    #pragma unroll
    for (int i = 0; i < 4; i++) {
        int m = m0 + (ty << 2) + i;
        if (m >= M) continue;
        #pragma unroll
        for (int j = 0; j < 4; j++) {
            int n = n0 + (tx << 2) + j;
            if (n >= N) continue;
            float c = acc[i][j] + bp[n];
            if (act == 1) c = c / (1.f + __expf(-c));
            Cp[(size_t)m * ldc + n] = c;
        }
    }
}

// ---------------- combine: out += w0*ye[slot0] + w1*ye[slot1] ----------------
__global__ __launch_bounds__(256) void combine_kernel(float* __restrict__ hout)
{
    int tok = blockIdx.x;
    int j = threadIdx.x << 2;
    int s0 = g_slot[tok * 2], s1 = g_slot[tok * 2 + 1];
    float w0 = g_wgt[tok * 2], w1 = g_wgt[tok * 2 + 1];
    float4 a  = *(float4*)&hout[(size_t)tok * DD + j];
    float4 y0 = *(const float4*)&g_ye[(size_t)s0 * DD + j];
    float4 y1 = *(const float4*)&g_ye[(size_t)s1 * DD + j];
    a.x += w0 * y0.x + w1 * y1.x;
    a.y += w0 * y0.y + w1 * y1.y;
    a.z += w0 * y0.z + w1 * y1.z;
    a.w += w0 * y0.w + w1 * y1.w;
    *(float4*)&hout[(size_t)tok * DD + j] = a;
}

// ---------------- launcher ----------------
extern "C" void kernel_launch(void* const* d_in, const int* in_sizes, int n_in,
                              void* d_out, int out_size)
{
    const float* x        = (const float*)d_in[0];
    const float* lnm_g    = (const float*)d_in[1];
    const float* lnm_b    = (const float*)d_in[2];
    const float* lne_g    = (const float*)d_in[3];
    const float* lne_b    = (const float*)d_in[4];
    const float* in_w     = (const float*)d_in[5];
    const float* in_b     = (const float*)d_in[6];
    const float* conv_w   = (const float*)d_in[7];
    const float* conv_b   = (const float*)d_in[8];
    const float* xproj_w  = (const float*)d_in[9];
    const float* dt_w     = (const float*)d_in[10];
    const float* dt_b     = (const float*)d_in[11];
    const float* A_log    = (const float*)d_in[12];
    const float* D_skip   = (const float*)d_in[13];
    const float* out_w    = (const float*)d_in[14];
    const float* router_w = (const float*)d_in[15];
    const float* w1       = (const float*)d_in[16];
    const float* b1       = (const float*)d_in[17];
    const float* w2       = (const float*)d_in[18];
    const float* b2       = (const float*)d_in[19];

    float* out_h     = (float*)d_out;
    float* out_probs = out_h + (size_t)TOK * DD;

    float *hnorm, *xz, *xc, *proj, *dtb, *yb, *hmoein, *h1, *ye;
    cudaGetSymbolAddress((void**)&hnorm,  g_hnorm);
    cudaGetSymbolAddress((void**)&xz,     g_xz);
    cudaGetSymbolAddress((void**)&xc,     g_xc);
    cudaGetSymbolAddress((void**)&proj,   g_proj);
    cudaGetSymbolAddress((void**)&dtb,    g_dt);
    cudaGetSymbolAddress((void**)&yb,     g_y);
    cudaGetSymbolAddress((void**)&hmoein, g_hmoein);
    cudaGetSymbolAddress((void**)&h1,     g_h1);
    cudaGetSymbolAddress((void**)&ye,     g_ye);

    // 1. LN (mamba)
    ln_kernel<<<TOK, 256>>>(x, hnorm, lnm_g, lnm_b);
    // 2. in_proj: xz = hnorm @ in_w^T + in_b   (4096 x 4096 x 1024)
    gemm_nt<<<dim3(XZN/64, TOK/64), 256>>>(hnorm, DD, in_w, DD, xz, XZN,
                                           TOK, XZN, DD, in_b, nullptr, 0);
    // 3. conv + silu
    conv_silu_kernel<<<(TOK*DI)/256, 256>>>(xz, conv_w, conv_b, xc);
    // 4. x_proj: proj = xc @ xproj_w^T   (4096 x 96 x 2048)
    gemm_nt<<<dim3(2, TOK/64), 256>>>(xc, DI, xproj_w, DI, proj, PROJN,
                                      TOK, PROJN, DI, nullptr, nullptr, 0);
    // 5. dt = softplus(dt_r @ dt_w^T + dt_b)   (4096 x 2048 x 64), dt_r = proj[:, :64]
    gemm_nt<<<dim3(DI/64, TOK/64), 256>>>(proj, PROJN, dt_w, DTR, dtb, DI,
                                          TOK, DI, DTR, dt_b, nullptr, 2);
    // 6. selective scan + skip + gate
    scan_kernel<<<dim3(32, BATCH), 256>>>(proj, xc, dtb, xz, A_log, D_skip, yb);
    // 7. out_proj + residual x -> h (into d_out)
    gemm_nt<<<dim3(DD/64, TOK/64), 256>>>(yb, DI, out_w, DI, out_h, DD,
                                          TOK, DD, DI, nullptr, x, 0);
    // 8. LN (moe)
    ln_kernel<<<TOK, 256>>>(out_h, hmoein, lne_g, lne_b);
    // 9. router / top2 / expert lists
    zero_cnt_kernel<<<1, 32>>>();
    router_kernel<<<TOK/8, 256>>>(hmoein, router_w, out_probs);
    // 10. expert GEMM 1: h1 = silu(X_gather @ w1^T + b1)
    moe_gemm<<<dim3(DFF/64, CAP/64, NE), 256>>>(hmoein, DD, 0,
                                                w1, DD, (size_t)DFF * DD,
                                                h1, DFF, (size_t)CAP * DFF,
                                                DFF, DD, b1, DFF, 1, 1);
    // 11. expert GEMM 2: ye = h1 @ w2^T + b2
    moe_gemm<<<dim3(DD/64, CAP/64, NE), 256>>>(h1, DFF, (size_t)CAP * DFF,
                                               w2, DFF, (size_t)DD * DFF,
                                               ye, DD, (size_t)CAP * DD,
                                               DD, DFF, b2, DD, 0, 0);
    // 12. combine
    combine_kernel<<<TOK, 256>>>(out_h);
}

// round 3
// speedup vs baseline: 1.5356x; 1.5356x over previous
#include <cuda_runtime.h>
#include <cuda_bf16.h>
#include <cstdint>
#include <math.h>

// ---------------- problem constants ----------------
#define BATCH 2
#define TT    2048
#define TOK   4096          // BATCH*TT
#define DD    1024
#define DI    2048
#define XZN   4096          // 2*DI
#define NSTATE 16
#define DTR   64
#define PROJN 96            // DTR + 2*NSTATE
#define DFF   2048
#define NE    8
#define CAP   4096          // max tokens per expert

// ---------------- unified scratch (single symbol; no allocs) ----------------
constexpr size_t O_XZ   = 0;
constexpr size_t O_XC   = O_XZ   + (size_t)TOK*XZN*4;
constexpr size_t O_HN   = O_XC   + (size_t)TOK*DI*4;
constexpr size_t O_PROJ = O_HN   + (size_t)TOK*DD*4;
constexpr size_t O_DT   = O_PROJ + (size_t)TOK*PROJN*4;
constexpr size_t O_Y    = O_DT   + (size_t)TOK*DI*4;
constexpr size_t O_HM   = O_Y    + (size_t)TOK*DI*4;
constexpr size_t O_YE   = O_HM   + (size_t)TOK*DD*4;
constexpr size_t O_HNH  = O_YE   + (size_t)NE*CAP*DD*4;
constexpr size_t O_HNL  = O_HNH  + (size_t)TOK*DD*2;
constexpr size_t O_INWH = O_HNL  + (size_t)TOK*DD*2;
constexpr size_t O_INWL = O_INWH + (size_t)XZN*DD*2;
constexpr size_t O_XCH  = O_INWL + (size_t)XZN*DD*2;
constexpr size_t O_XCL  = O_XCH  + (size_t)TOK*DI*2;
constexpr size_t O_XPWH = O_XCL  + (size_t)TOK*DI*2;
constexpr size_t O_XPWL = O_XPWH + (size_t)128*DI*2;
constexpr size_t O_DTAH = O_XPWL + (size_t)128*DI*2;
constexpr size_t O_DTAL = O_DTAH + (size_t)TOK*DTR*2;
constexpr size_t O_DTWH = O_DTAL + (size_t)TOK*DTR*2;
constexpr size_t O_DTWL = O_DTWH + (size_t)DI*DTR*2;
constexpr size_t O_YBH  = O_DTWL + (size_t)DI*DTR*2;
constexpr size_t O_YBL  = O_YBH  + (size_t)TOK*DI*2;
constexpr size_t O_OWH  = O_YBL  + (size_t)TOK*DI*2;
constexpr size_t O_OWL  = O_OWH  + (size_t)DD*DI*2;
constexpr size_t O_HMH  = O_OWL  + (size_t)DD*DI*2;
constexpr size_t O_HML  = O_HMH  + (size_t)TOK*DD*2;
constexpr size_t O_W1H  = O_HML  + (size_t)TOK*DD*2;
constexpr size_t O_W1L  = O_W1H  + (size_t)NE*DFF*DD*2;
constexpr size_t O_W2H  = O_W1L  + (size_t)NE*DFF*DD*2;
constexpr size_t O_W2L  = O_W2H  + (size_t)NE*DD*DFF*2;
constexpr size_t O_H1H  = O_W2L  + (size_t)NE*DD*DFF*2;
constexpr size_t O_H1L  = O_H1H  + (size_t)NE*CAP*DFF*2;
constexpr size_t SCRATCH_BYTES = O_H1L + (size_t)NE*CAP*DFF*2;

__device__ __align__(256) unsigned char g_scratch[SCRATCH_BYTES];
__device__ int   g_cnt[NE];
__device__ int   g_list[NE * CAP];
__device__ int   g_slot[TOK * 2];
__device__ float g_wgt[TOK * 2];

// ---------------- PTX helpers (baseline sm_80-class, valid on sm_103) ----------
__device__ __forceinline__ uint32_t smem_u32(const void* p) {
    uint32_t a;
    asm("{ .reg .u64 t; cvta.to.shared.u64 t, %1; cvt.u32.u64 %0, t; }" : "=r"(a) : "l"(p));
    return a;
}
__device__ __forceinline__ void cpa16(uint32_t dst, const void* src, bool valid) {
    int sz = valid ? 16 : 0;
    asm volatile("cp.async.ca.shared.global [%0], [%1], 16, %2;"
                 :: "r"(dst), "l"(src), "r"(sz) : "memory");
}
#define CP_COMMIT() asm volatile("cp.async.commit_group;" ::: "memory")
#define CP_WAIT1()  asm volatile("cp.async.wait_group 1;" ::: "memory")
#define CP_WAIT0()  asm volatile("cp.async.wait_group 0;" ::: "memory")

__device__ __forceinline__ void ldsm_x4(uint32_t* r, uint32_t addr) {
    asm volatile("ldmatrix.sync.aligned.m8n8.x4.shared.b16 {%0,%1,%2,%3}, [%4];"
                 : "=r"(r[0]), "=r"(r[1]), "=r"(r[2]), "=r"(r[3]) : "r"(addr));
}
__device__ __forceinline__ void ldsm_x2(uint32_t* r, uint32_t addr) {
    asm volatile("ldmatrix.sync.aligned.m8n8.x2.shared.b16 {%0,%1}, [%2];"
                 : "=r"(r[0]), "=r"(r[1]) : "r"(addr));
}
__device__ __forceinline__ void mma16816(float* c, const uint32_t* a, const uint32_t* b) {
    asm volatile(
        "mma.sync.aligned.m16n8k16.row.col.f32.bf16.bf16.f32 "
        "{%0,%1,%2,%3}, {%4,%5,%6,%7}, {%8,%9}, {%0,%1,%2,%3};"
        : "+f"(c[0]), "+f"(c[1]), "+f"(c[2]), "+f"(c[3])
        : "r"(a[0]), "r"(a[1]), "r"(a[2]), "r"(a[3]), "r"(b[0]), "r"(b[1]));
}

// ---------------- fp32 -> bf16 hi/lo split (with pad/zero-fill) ----------------
__global__ __launch_bounds__(256) void split_kernel(
    const float* __restrict__ src, int srcRows, int srcCols, int lda,
    __nv_bfloat16* __restrict__ hi, __nv_bfloat16* __restrict__ lo,
    int ldd, long long total)
{
    long long idx = (long long)blockIdx.x * 256 + threadIdx.x;
    if (idx >= total) return;
    int r = (int)(idx / ldd), c = (int)(idx % ldd);
    float v = (r < srcRows && c < srcCols) ? src[(size_t)r * lda + c] : 0.f;
    __nv_bfloat16 h = __float2bfloat16(v);
    hi[idx] = h;
    lo[idx] = __float2bfloat16(v - __bfloat162float(h));
}

// ---------------- tensor-core GEMM: C[M,N] = A[M,K] @ B[N,K]^T ----------------
// bf16 hi/lo 3-term split (hh + hl + lh), fp32 accumulate via mma.sync m16n8k16.
// Block tile 128x128, 8 warps of 64x32, K-chunk 32, cp.async double buffer.
#define RS 40                       // smem row stride in bf16 elems (80B, conflict-free)
#define TILE_B (128 * RS * 2)       // one 128x32 tile: 10240 B
#define STAGE_B (4 * TILE_B)        // Ah,Al,Bh,Bl: 40960 B
#define TG_SMEM (2 * STAGE_B)       // 81920 B

__global__ __launch_bounds__(256) void tgemm(
    const __nv_bfloat16* __restrict__ Ahi, const __nv_bfloat16* __restrict__ Alo,
    int lda, unsigned long long sA,
    const __nv_bfloat16* __restrict__ Bhi, const __nv_bfloat16* __restrict__ Blo,
    int ldb, unsigned long long sB,
    float* __restrict__ C, int ldc, unsigned long long sC,
    __nv_bfloat16* __restrict__ Chi, __nv_bfloat16* __restrict__ Clo,
    int Mfixed, int Nreal, int K,
    const float* __restrict__ bias, int sBias,
    const float* __restrict__ resid,
    int act, int gather, int useCnt)
{
    extern __shared__ char sm[];
    int tid = threadIdx.x, wid = tid >> 5, lane = tid & 31;
    int e = blockIdx.z;
    int M = useCnt ? g_cnt[e] : Mfixed;
    int m0 = blockIdx.y * 128, n0 = blockIdx.x * 128;
    if (m0 >= M) return;

    uint32_t smb = smem_u32(sm);

    // ---- loader mapping: thread -> row r=tid>>1, half=(tid&1) of 32-elem row ----
    int lrow = tid >> 1;
    int half = tid & 1;                 // 16-elem half
    int am = m0 + lrow;
    bool av = am < M;
    size_t arow = gather ? (av ? (size_t)g_list[e * CAP + am] : 0) : (size_t)am;
    const __nv_bfloat16* pAh = Ahi + (size_t)e * sA + arow * (size_t)lda + half * 16;
    const __nv_bfloat16* pAl = Alo + (size_t)e * sA + arow * (size_t)lda + half * 16;
    const __nv_bfloat16* pBh = Bhi + (size_t)e * sB + (size_t)(n0 + lrow) * ldb + half * 16;
    const __nv_bfloat16* pBl = Blo + (size_t)e * sB + (size_t)(n0 + lrow) * ldb + half * 16;
    uint32_t dstRow = (uint32_t)(lrow * RS + half * 16) * 2;   // bytes within tile

    int kTiles = K >> 5;  // 32-elem chunks

    auto issue_stage = [&](int kt, int stage) {
        uint32_t base = smb + stage * STAGE_B + dstRow;
        int koff = kt << 5;
        cpa16(base,                       pAh + koff,      av);
        cpa16(base + 16,                  pAh + koff + 8,  av);
        cpa16(base + TILE_B,              pAl + koff,      av);
        cpa16(base + TILE_B + 16,         pAl + koff + 8,  av);
        cpa16(base + 2 * TILE_B,          pBh + koff,      true);
        cpa16(base + 2 * TILE_B + 16,     pBh + koff + 8,  true);
        cpa16(base + 3 * TILE_B,          pBl + koff,      true);
        cpa16(base + 3 * TILE_B + 16,     pBl + koff + 8,  true);
        CP_COMMIT();
    };

    float acc[4][4][4] = {};
    int wm = wid >> 2, wn = wid & 3;    // 2x4 warp grid; warp tile 64x32

    // ldmatrix source addresses (byte offsets inside a stage)
    // A: rows m, x4 over (m 0..15, k 0..15): addr = (mIdx*RS + kk + (lane>>4)*8)*2
    uint32_t aRowSel = (uint32_t)(wm * 64 + (lane & 15)) * RS + ((lane >> 4) << 3);
    // B: x2 over (n 0..7, k 0..15): addr = (nIdx*RS + kk + ((lane>>3)&1)*8)*2
    uint32_t bRowSel = (uint32_t)(wn * 32 + (lane & 7)) * RS + (((lane >> 3) & 1) << 3);

    issue_stage(0, 0);

    for (int kt = 0; kt < kTiles; kt++) {
        if (kt + 1 < kTiles) issue_stage(kt + 1, (kt + 1) & 1);
        else CP_COMMIT();  // keep group count in sync
        CP_WAIT1();
        __syncthreads();

        uint32_t stb = smb + (kt & 1) * STAGE_B;
        #pragma unroll
        for (int kk = 0; kk < 2; kk++) {
            uint32_t ah[4][4], al[4][4], bh[4][2], bl[4][2];
            #pragma unroll
            for (int mi = 0; mi < 4; mi++) {
                uint32_t aoff = stb + (aRowSel + (uint32_t)mi * 16 * RS + kk * 16) * 2;
                ldsm_x4(ah[mi], aoff);
                ldsm_x4(al[mi], aoff + TILE_B);
            }
            #pragma unroll
            for (int ni = 0; ni < 4; ni++) {
                uint32_t boff = stb + 2 * TILE_B + (bRowSel + (uint32_t)ni * 8 * RS + kk * 16) * 2;
                ldsm_x2(bh[ni], boff);
                ldsm_x2(bl[ni], boff + TILE_B);
            }
            #pragma unroll
            for (int mi = 0; mi < 4; mi++)
                #pragma unroll
                for (int ni = 0; ni < 4; ni++) {
                    mma16816(acc[mi][ni], ah[mi], bh[ni]);
                    mma16816(acc[mi][ni], ah[mi], bl[ni]);
                    mma16816(acc[mi][ni], al[mi], bh[ni]);
                }
        }
        __syncthreads();
    }

    // ---- epilogue ----
    int r0 = lane >> 2, c0 = (lane & 3) << 1;
    const float* bp = bias ? bias + (size_t)e * sBias : nullptr;
    #pragma unroll
    for (int mi = 0; mi < 4; mi++) {
        #pragma unroll
        for (int ni = 0; ni < 4; ni++) {
            #pragma unroll
            for (int q = 0; q < 4; q++) {
                int m = m0 + wm * 64 + mi * 16 + r0 + (q >> 1) * 8;
                int n = n0 + wn * 32 + ni * 8 + c0 + (q & 1);
                if (m >= M || n >= Nreal) continue;
                float v = acc[mi][ni][q];
                if (bp)    v += bp[n];
                if (resid) v += resid[(size_t)m * ldc + n];
                if (act == 1)      v = v / (1.f + __expf(-v));
                else if (act == 2) v = (v > 20.f) ? v : log1pf(__expf(v));
                size_t off = (size_t)e * sC + (size_t)m * ldc + n;
                if (C) C[off] = v;
                if (Chi) {
                    __nv_bfloat16 h = __float2bfloat16(v);
                    Chi[off] = h;
                    Clo[off] = __float2bfloat16(v - __bfloat162float(h));
                }
            }
        }
    }
}

// ---------------- LayerNorm ----------------
__global__ __launch_bounds__(256) void ln_kernel(
    const float* __restrict__ x, float* __restrict__ out,
    const float* __restrict__ g, const float* __restrict__ b)
{
    int tok = blockIdx.x;
    int i = threadIdx.x << 2;
    const float* xr = x + (size_t)tok * DD;
    float4 v = *(const float4*)&xr[i];
    float s  = v.x + v.y + v.z + v.w;
    float s2 = v.x*v.x + v.y*v.y + v.z*v.z + v.w*v.w;
    #pragma unroll
    for (int o = 16; o > 0; o >>= 1) {
        s  += __shfl_xor_sync(0xffffffffu, s,  o);
        s2 += __shfl_xor_sync(0xffffffffu, s2, o);
    }
    __shared__ float sh[16];
    int w = threadIdx.x >> 5;
    if ((threadIdx.x & 31) == 0) { sh[w] = s; sh[8 + w] = s2; }
    __syncthreads();
    s = 0.f; s2 = 0.f;
    #pragma unroll
    for (int k = 0; k < 8; k++) { s += sh[k]; s2 += sh[8 + k]; }
    float mu  = s * (1.0f / DD);
    float var = s2 * (1.0f / DD) - mu * mu;
    float rr = rsqrtf(var + 1e-5f);
    float4 gv = *(const float4*)&g[i];
    float4 bv = *(const float4*)&b[i];
    float4 o4;
    o4.x = (v.x - mu) * rr * gv.x + bv.x;
    o4.y = (v.y - mu) * rr * gv.y + bv.y;
    o4.z = (v.z - mu) * rr * gv.z + bv.z;
    o4.w = (v.w - mu) * rr * gv.w + bv.w;
    *(float4*)&out[(size_t)tok * DD + i] = o4;
}

// ---------------- causal depthwise conv (KC=4) + SiLU ----------------
__global__ __launch_bounds__(256) void conv_silu_kernel(
    const float* __restrict__ xz,
    const float* __restrict__ cw,
    const float* __restrict__ cb,
    float* __restrict__ xc)
{
    int idx = blockIdx.x * 256 + threadIdx.x;
    int d = idx & (DI - 1);
    int m = idx >> 11;
    int t = m & (TT - 1);
    float acc = cb[d];
    float4 w = *(const float4*)&cw[d * 4];
    const float* base = xz + (size_t)m * XZN + d;
    if (t >= 3) acc += w.x * base[-3 * XZN];
    if (t >= 2) acc += w.y * base[-2 * XZN];
    if (t >= 1) acc += w.z * base[-XZN];
    acc += w.w * base[0];
    xc[idx] = acc / (1.f + __expf(-acc));
}

// ---------------- selective scan ----------------
__global__ __launch_bounds__(256) void scan_kernel(
    const float* __restrict__ proj,
    const float* __restrict__ xc,
    const float* __restrict__ dt,
    const float* __restrict__ xz,
    const float* __restrict__ A_log,
    const float* __restrict__ D_skip,
    float* __restrict__ ybuf)
{
    int b = blockIdx.y;
    int lane = threadIdx.x & 31;
    int ch = lane >> 2, ng = lane & 3;
    int d = (blockIdx.x * 8 + (threadIdx.x >> 5)) * 8 + ch;

    float4 Al = *(const float4*)&A_log[(size_t)d * NSTATE + ng * 4];
    float a0 = -__expf(Al.x), a1 = -__expf(Al.y), a2 = -__expf(Al.z), a3 = -__expf(Al.w);
    float h0 = 0.f, h1 = 0.f, h2 = 0.f, h3 = 0.f;
    float dsk = D_skip[d];
    size_t tokbase = (size_t)b * TT;

    for (int t = 0; t < TT; t++) {
        size_t tok = tokbase + t;
        float4 Bv = *(const float4*)&proj[tok * PROJN + DTR + ng * 4];
        float4 Cv = *(const float4*)&proj[tok * PROJN + DTR + NSTATE + ng * 4];
        float xt  = xc[tok * DI + d];
        float dtt = dt[tok * DI + d];
        float dx  = dtt * xt;
        h0 = __expf(dtt * a0) * h0 + dx * Bv.x;
        h1 = __expf(dtt * a1) * h1 + dx * Bv.y;
        h2 = __expf(dtt * a2) * h2 + dx * Bv.z;
        h3 = __expf(dtt * a3) * h3 + dx * Bv.w;
        float y = h0 * Cv.x + h1 * Cv.y + h2 * Cv.z + h3 * Cv.w;
        y += __shfl_xor_sync(0xffffffffu, y, 1);
        y += __shfl_xor_sync(0xffffffffu, y, 2);
        if (ng == 0) {
            float z = xz[tok * XZN + DI + d];
            float sil = z / (1.f + __expf(-z));
            ybuf[tok * DI + d] = (y + xt * dsk) * sil;
        }
    }
}

// ---------------- router: softmax + top2 + expert list build ----------------
__global__ __launch_bounds__(256) void router_kernel(
    const float* __restrict__ xin,
    const float* __restrict__ rw,
    float* __restrict__ probs_out)
{
    int warp = threadIdx.x >> 5, lane = threadIdx.x & 31;
    int tok = blockIdx.x * 8 + warp;
    const float* xr = xin + (size_t)tok * DD;
    float acc[8] = {};
    for (int c = lane; c < DD; c += 32) {
        float xv = xr[c];
        #pragma unroll
        for (int e = 0; e < 8; e++) acc[e] += xv * rw[e * DD + c];
    }
    #pragma unroll
    for (int e = 0; e < 8; e++)
        #pragma unroll
        for (int o = 16; o > 0; o >>= 1) acc[e] += __shfl_xor_sync(0xffffffffu, acc[e], o);
    if (lane == 0) {
        float mx = acc[0];
        #pragma unroll
        for (int e = 1; e < 8; e++) mx = fmaxf(mx, acc[e]);
        float p[8], s = 0.f;
        #pragma unroll
        for (int e = 0; e < 8; e++) { p[e] = __expf(acc[e] - mx); s += p[e]; }
        float inv = 1.f / s;
        #pragma unroll
        for (int e = 0; e < 8; e++) { p[e] *= inv; probs_out[(size_t)tok * 8 + e] = p[e]; }
        int i0 = 0; float v0 = p[0];
        #pragma unroll
        for (int e = 1; e < 8; e++) if (p[e] > v0) { v0 = p[e]; i0 = e; }
        int i1 = -1; float v1 = -1.f;
        #pragma unroll
        for (int e = 0; e < 8; e++) if (e != i0 && p[e] > v1) { v1 = p[e]; i1 = e; }
        float wn = 1.f / (v0 + v1);
        int p0 = atomicAdd(&g_cnt[i0], 1);
        int p1 = atomicAdd(&g_cnt[i1], 1);
        g_list[i0 * CAP + p0] = tok;
        g_list[i1 * CAP + p1] = tok;
        g_slot[tok * 2 + 0] = i0 * CAP + p0;
        g_slot[tok * 2 + 1] = i1 * CAP + p1;
        g_wgt[tok * 2 + 0] = v0 * wn;
        g_wgt[tok * 2 + 1] = v1 * wn;
    }
}

__global__ void zero_cnt_kernel() { if (threadIdx.x < NE) g_cnt[threadIdx.x] = 0; }

// ---------------- combine: out += w0*ye[slot0] + w1*ye[slot1] ----------------
__global__ __launch_bounds__(256) void combine_kernel(float* __restrict__ hout,
                                                      const float* __restrict__ ye)
{
    int tok = blockIdx.x;
    int j = threadIdx.x << 2;
    int s0 = g_slot[tok * 2], s1 = g_slot[tok * 2 + 1];
    float w0 = g_wgt[tok * 2], w1 = g_wgt[tok * 2 + 1];
    float4 a  = *(float4*)&hout[(size_t)tok * DD + j];
    float4 y0 = *(const float4*)&ye[(size_t)s0 * DD + j];
    float4 y1 = *(const float4*)&ye[(size_t)s1 * DD + j];
    a.x += w0 * y0.x + w1 * y1.x;
    a.y += w0 * y0.y + w1 * y1.y;
    a.z += w0 * y0.z + w1 * y1.z;
    a.w += w0 * y0.w + w1 * y1.w;
    *(float4*)&hout[(size_t)tok * DD + j] = a;
}

// ---------------- launcher ----------------
static inline int splitBlocks(long long total) { return (int)((total + 255) / 256); }

extern "C" void kernel_launch(void* const* d_in, const int* in_sizes, int n_in,
                              void* d_out, int out_size)
{
    const float* x        = (const float*)d_in[0];
    const float* lnm_g    = (const float*)d_in[1];
    const float* lnm_b    = (const float*)d_in[2];
    const float* lne_g    = (const float*)d_in[3];
    const float* lne_b    = (const float*)d_in[4];
    const float* in_w     = (const float*)d_in[5];
    const float* in_b     = (const float*)d_in[6];
    const float* conv_w   = (const float*)d_in[7];
    const float* conv_b   = (const float*)d_in[8];
    const float* xproj_w  = (const float*)d_in[9];
    const float* dt_w     = (const float*)d_in[10];
    const float* dt_b     = (const float*)d_in[11];
    const float* A_log    = (const float*)d_in[12];
    const float* D_skip   = (const float*)d_in[13];
    const float* out_w    = (const float*)d_in[14];
    const float* router_w = (const float*)d_in[15];
    const float* w1       = (const float*)d_in[16];
    const float* b1       = (const float*)d_in[17];
    const float* w2       = (const float*)d_in[18];
    const float* b2       = (const float*)d_in[19];

    float* out_h     = (float*)d_out;
    float* out_probs = out_h + (size_t)TOK * DD;

    unsigned char* S;
    cudaGetSymbolAddress((void**)&S, g_scratch);
    float* xz    = (float*)(S + O_XZ);
    float* xc    = (float*)(S + O_XC);
    float* hn    = (float*)(S + O_HN);
    float* proj  = (float*)(S + O_PROJ);
    float* dtb   = (float*)(S + O_DT);
    float* yb    = (float*)(S + O_Y);
    float* hm    = (float*)(S + O_HM);
    float* ye    = (float*)(S + O_YE);
    __nv_bfloat16* hnh  = (__nv_bfloat16*)(S + O_HNH);
    __nv_bfloat16* hnl  = (__nv_bfloat16*)(S + O_HNL);
    __nv_bfloat16* inwh = (__nv_bfloat16*)(S + O_INWH);
    __nv_bfloat16* inwl = (__nv_bfloat16*)(S + O_INWL);
    __nv_bfloat16* xch  = (__nv_bfloat16*)(S + O_XCH);
    __nv_bfloat16* xcl  = (__nv_bfloat16*)(S + O_XCL);
    __nv_bfloat16* xpwh = (__nv_bfloat16*)(S + O_XPWH);
    __nv_bfloat16* xpwl = (__nv_bfloat16*)(S + O_XPWL);
    __nv_bfloat16* dtah = (__nv_bfloat16*)(S + O_DTAH);
    __nv_bfloat16* dtal = (__nv_bfloat16*)(S + O_DTAL);
    __nv_bfloat16* dtwh = (__nv_bfloat16*)(S + O_DTWH);
    __nv_bfloat16* dtwl = (__nv_bfloat16*)(S + O_DTWL);
    __nv_bfloat16* ybh  = (__nv_bfloat16*)(S + O_YBH);
    __nv_bfloat16* ybl  = (__nv_bfloat16*)(S + O_YBL);
    __nv_bfloat16* owh  = (__nv_bfloat16*)(S + O_OWH);
    __nv_bfloat16* owl  = (__nv_bfloat16*)(S + O_OWL);
    __nv_bfloat16* hmh  = (__nv_bfloat16*)(S + O_HMH);
    __nv_bfloat16* hml  = (__nv_bfloat16*)(S + O_HML);
    __nv_bfloat16* w1h  = (__nv_bfloat16*)(S + O_W1H);
    __nv_bfloat16* w1l  = (__nv_bfloat16*)(S + O_W1L);
    __nv_bfloat16* w2h  = (__nv_bfloat16*)(S + O_W2H);
    __nv_bfloat16* w2l  = (__nv_bfloat16*)(S + O_W2L);
    __nv_bfloat16* h1h  = (__nv_bfloat16*)(S + O_H1H);
    __nv_bfloat16* h1l  = (__nv_bfloat16*)(S + O_H1L);

    cudaFuncSetAttribute(tgemm, cudaFuncAttributeMaxDynamicSharedMemorySize, TG_SMEM);

    // 1. LN (mamba)
    ln_kernel<<<TOK, 256>>>(x, hn, lnm_g, lnm_b);
    // 2. splits for in_proj
    split_kernel<<<splitBlocks((long long)TOK*DD), 256>>>(hn, TOK, DD, DD, hnh, hnl, DD, (long long)TOK*DD);
    split_kernel<<<splitBlocks((long long)XZN*DD), 256>>>(in_w, XZN, DD, DD, inwh, inwl, DD, (long long)XZN*DD);
    // 3. in_proj: xz = hn @ in_w^T + in_b
    tgemm<<<dim3(XZN/128, TOK/128, 1), 256, TG_SMEM>>>(
        hnh, hnl, DD, 0, inwh, inwl, DD, 0,
        xz, XZN, 0, nullptr, nullptr,
        TOK, XZN, DD, in_b, 0, nullptr, 0, 0, 0);
    // 4. conv + silu
    conv_silu_kernel<<<(TOK*DI)/256, 256>>>(xz, conv_w, conv_b, xc);
    // 5. splits for x_proj (pad B rows 96 -> 128 with zeros)
    split_kernel<<<splitBlocks((long long)TOK*DI), 256>>>(xc, TOK, DI, DI, xch, xcl, DI, (long long)TOK*DI);
    split_kernel<<<splitBlocks((long long)128*DI), 256>>>(xproj_w, PROJN, DI, DI, xpwh, xpwl, DI, (long long)128*DI);
    // 6. x_proj: proj = xc @ xproj_w^T
    tgemm<<<dim3(1, TOK/128, 1), 256, TG_SMEM>>>(
        xch, xcl, DI, 0, xpwh, xpwl, DI, 0,
        proj, PROJN, 0, nullptr, nullptr,
        TOK, PROJN, DI, nullptr, 0, nullptr, 0, 0, 0);
    // 7. splits for dt_proj (A = proj[:, :64], strided)
    split_kernel<<<splitBlocks((long long)TOK*DTR), 256>>>(proj, TOK, DTR, PROJN, dtah, dtal, DTR, (long long)TOK*DTR);
    split_kernel<<<splitBlocks((long long)DI*DTR), 256>>>(dt_w, DI, DTR, DTR, dtwh, dtwl, DTR, (long long)DI*DTR);
    // 8. dt = softplus(dt_r @ dt_w^T + dt_b)
    tgemm<<<dim3(DI/128, TOK/128, 1), 256, TG_SMEM>>>(
        dtah, dtal, DTR, 0, dtwh, dtwl, DTR, 0,
        dtb, DI, 0, nullptr, nullptr,
        TOK, DI, DTR, dt_b, 0, nullptr, 2, 0, 0);
    // 9. selective scan + skip + gate
    scan_kernel<<<dim3(32, BATCH), 256>>>(proj, xc, dtb, xz, A_log, D_skip, yb);
    // 10. splits for out_proj
    split_kernel<<<splitBlocks((long long)TOK*DI), 256>>>(yb, TOK, DI, DI, ybh, ybl, DI, (long long)TOK*DI);
    split_kernel<<<splitBlocks((long long)DD*DI), 256>>>(out_w, DD, DI, DI, owh, owl, DI, (long long)DD*DI);
    // 11. out_proj + residual x -> h (d_out)
    tgemm<<<dim3(DD/128, TOK/128, 1), 256, TG_SMEM>>>(
        ybh, ybl, DI, 0, owh, owl, DI, 0,
        out_h, DD, 0, nullptr, nullptr,
        TOK, DD, DI, nullptr, 0, x, 0, 0, 0);
    // 12. LN (moe)
    ln_kernel<<<TOK, 256>>>(out_h, hm, lne_g, lne_b);
    // 13. router / top2 / expert lists
    zero_cnt_kernel<<<1, 32>>>();
    router_kernel<<<TOK/8, 256>>>(hm, router_w, out_probs);
    // 14. splits for MoE
    split_kernel<<<splitBlocks((long long)TOK*DD), 256>>>(hm, TOK, DD, DD, hmh, hml, DD, (long long)TOK*DD);
    split_kernel<<<splitBlocks((long long)NE*DFF*DD), 256>>>(w1, NE*DFF, DD, DD, w1h, w1l, DD, (long long)NE*DFF*DD);
    split_kernel<<<splitBlocks((long long)NE*DD*DFF), 256>>>(w2, NE*DD, DFF, DFF, w2h, w2l, DFF, (long long)NE*DD*DFF);
    // 15. expert GEMM 1: h1(split) = silu(gather(hm) @ w1^T + b1)
    tgemm<<<dim3(DFF/128, CAP/128, NE), 256, TG_SMEM>>>(
        hmh, hml, DD, 0, w1h, w1l, DD, (unsigned long long)DFF*DD,
        nullptr, DFF, (unsigned long long)CAP*DFF, h1h, h1l,
        0, DFF, DD, b1, DFF, nullptr, 1, 1, 1);
    // 16. expert GEMM 2: ye = h1 @ w2^T + b2
    tgemm<<<dim3(DD/128, CAP/128, NE), 256, TG_SMEM>>>(
        h1h, h1l, DFF, (unsigned long long)CAP*DFF, w2h, w2l, DFF, (unsigned long long)DD*DFF,
        ye, DD, (unsigned long long)CAP*DD, nullptr, nullptr,
        0, DD, DFF, b2, DD, nullptr, 0, 0, 1);
    // 17. combine
    combine_kernel<<<TOK, 256>>>(out_h, ye);
}